// round 3
// baseline (speedup 1.0000x reference)
#include <cuda_runtime.h>

#define Bb 64
#define Tt 512
#define Ee 256
#define Uu 512
#define NG 2048   // 4*U
#define NBLK 128  // step-kernel grid: CTA owns 4 u-columns (all 4 gates)

// Scratch (device globals: allocation-free per harness rules)
__device__ float g_xp[(size_t)Tt * NG * Bb];          // [t][n][b], n = gate*U + u (256 MB)
__device__ float g_h[2][Bb * Uu];                     // h double buffer (L2-resident)
__device__ float g_c[Bb * Uu];                        // cell state
__device__ unsigned long long g_wpack[NBLK * 4096];   // packed Wh, per-CTA slices (4 MB)

// ---------- packed f32x2 helpers (Blackwell FFMA2; ptxas never emits these) ----------
static __device__ __forceinline__ unsigned long long pack2(float a, float b) {
    unsigned long long r;
    unsigned ai = __float_as_uint(a), bi = __float_as_uint(b);
    asm("mov.b64 %0, {%1, %2};" : "=l"(r) : "r"(ai), "r"(bi));
    return r;
}
static __device__ __forceinline__ void unpack2(unsigned long long v, float& a, float& b) {
    unsigned ai, bi;
    asm("mov.b64 {%0, %1}, %2;" : "=r"(ai), "=r"(bi) : "l"(v));
    a = __uint_as_float(ai); b = __uint_as_float(bi);
}
static __device__ __forceinline__ unsigned long long ffma2(
    unsigned long long a, unsigned long long b, unsigned long long c) {
    unsigned long long d;
    asm("fma.rn.f32x2 %0, %1, %2, %3;" : "=l"(d) : "l"(a), "l"(b), "l"(c));
    return d;
}
static __device__ __forceinline__ float hadd2(unsigned long long v) {
    float a, b; unpack2(v, a, b); return a + b;
}

// =====================================================================================
// Kernel 1: x_proj. Per block: one t, 64x64 (b x n) tile, K=256 in 4 chunks of 64.
// Output layout xp[t][n][b] (+bias) so step kernels read b-contiguous columns.
// =====================================================================================
__global__ __launch_bounds__(256) void xproj_kernel(
    const float* __restrict__ inp,
    const float* __restrict__ W0, const float* __restrict__ W1,
    const float* __restrict__ W2, const float* __restrict__ W3,
    const float* __restrict__ b0, const float* __restrict__ b1,
    const float* __restrict__ b2, const float* __restrict__ b3)
{
    __shared__ float As[64][72];   // [b][e-chunk]
    __shared__ float Ws[64][72];   // [e-chunk][n]

    const int t     = blockIdx.y;
    const int ntile = blockIdx.x;        // 0..31
    const int gate  = ntile >> 3;
    const int u0    = (ntile & 7) << 6;
    const float* W    = (gate == 0) ? W0 : (gate == 1) ? W1 : (gate == 2) ? W2 : W3;
    const float* bias = (gate == 0) ? b0 : (gate == 1) ? b1 : (gate == 2) ? b2 : b3;

    const int tid = threadIdx.x;
    const int nq  = tid & 15;            // 4 consecutive n
    const int bq  = tid >> 4;            // 4 consecutive b

    unsigned long long acc[4][2];
    #pragma unroll
    for (int i = 0; i < 4; i++) { acc[i][0] = 0ull; acc[i][1] = 0ull; }

    for (int ec = 0; ec < Ee; ec += 64) {
        {   // A tile: inputs[b][t][ec..ec+63]
            int b = tid >> 2, q = tid & 3;
            const float4* src = (const float4*)(inp + ((size_t)b * Tt + t) * Ee + ec);
            float4* dst = (float4*)&As[b][0];
            #pragma unroll
            for (int i = 0; i < 4; i++) dst[q + i * 4] = src[q + i * 4];
        }
        {   // W tile: W[ec+e][u0..u0+63]
            int er = tid >> 4, n4 = (tid & 15) << 2;
            #pragma unroll
            for (int p = 0; p < 4; p++) {
                int e = er + p * 16;
                *(float4*)&Ws[e][n4] = *(const float4*)&W[(size_t)(ec + e) * Uu + u0 + n4];
            }
        }
        __syncthreads();
        #pragma unroll 4
        for (int e = 0; e < 64; e++) {
            ulonglong2 w = *(const ulonglong2*)&Ws[e][nq << 2];
            #pragma unroll
            for (int bi = 0; bi < 4; bi++) {
                float a = As[(bq << 2) + bi][e];
                unsigned long long aa = pack2(a, a);
                acc[bi][0] = ffma2(aa, w.x, acc[bi][0]);
                acc[bi][1] = ffma2(aa, w.y, acc[bi][1]);
            }
        }
        __syncthreads();
    }

    float r[4][4];
    #pragma unroll
    for (int bi = 0; bi < 4; bi++) {
        unpack2(acc[bi][0], r[bi][0], r[bi][1]);
        unpack2(acc[bi][1], r[bi][2], r[bi][3]);
    }
    size_t base = (size_t)t * NG * Bb
                + (size_t)(gate * Uu + u0 + (nq << 2)) * Bb + (bq << 2);
    #pragma unroll
    for (int nj = 0; nj < 4; nj++) {
        float bv = bias[u0 + (nq << 2) + nj];
        float4 v = make_float4(r[0][nj] + bv, r[1][nj] + bv, r[2][nj] + bv, r[3][nj] + bv);
        *(float4*)&g_xp[base + (size_t)nj * Bb] = v;
    }
}

// =====================================================================================
// Kernel 2: pack recurrent weights once into per-CTA slices.
// Layout: g_wpack[blk*4096 + p*16 + ul*4 + g] = (W_g[2p][u], W_g[2p+1][u]), u = blk*4+ul
// so each step kernel can refill its smem tile with 16 fully coalesced LDG.64/thread.
// =====================================================================================
__global__ __launch_bounds__(256) void pack_kernel(
    const float* __restrict__ Wfh, const float* __restrict__ Wih,
    const float* __restrict__ Woh, const float* __restrict__ Wgh)
{
    const int blk = blockIdx.x;
    const int ubase = blk << 2;
    for (int i = threadIdx.x; i < 4096; i += 256) {
        int p = i >> 4, ul = (i >> 2) & 3, g = i & 3;
        int u = ubase + ul;
        const float* W = (g == 0) ? Wfh : (g == 1) ? Wih : (g == 2) ? Woh : Wgh;
        g_wpack[(size_t)blk * 4096 + i] =
            pack2(W[(size_t)(2 * p) * Uu + u], W[(size_t)(2 * p + 1) * Uu + u]);
    }
}

// =====================================================================================
// Kernel 3: ONE TIMESTEP. Graph edge between consecutive launches is the global sync —
// no spin loops anywhere, correct for any SM count / residency. CTA owns 4 u-columns
// for all 4 gates; Wh slice refilled into smem from the packed L2-resident buffer.
// Thread = (b, ul): 4 f32x2 accumulators (consecutive-k pairs); h/c via L2 (__ldcg).
// =====================================================================================
__global__ __launch_bounds__(256) void lstm_step_kernel(float* __restrict__ out, int t)
{
    __shared__ unsigned long long whs[4096];          // [p][ul][g] k-pair weights (32 KB)
    const int tid = threadIdx.x;
    const int blk = blockIdx.x;

    {   // refill weight tile: fully coalesced, hits L2
        const unsigned long long* src = g_wpack + (size_t)blk * 4096;
        #pragma unroll
        for (int j = 0; j < 16; j++)
            whs[tid + j * 256] = __ldcg(src + tid + j * 256);
    }

    const int b  = tid >> 2;             // 4 lanes share a b (h LDG broadcast)
    const int ul = tid & 3;
    const int u  = (blk << 2) + ul;

    // issue xp/c loads now; consumed after the ~4K-cycle dot loop (latency hidden)
    const float* xpt = g_xp + (size_t)t * NG * Bb + (size_t)u * Bb + b;
    float zf = __ldg(xpt);
    float zi = __ldg(xpt + (size_t)(1 * Uu) * Bb);
    float zo = __ldg(xpt + (size_t)(2 * Uu) * Bb);
    float zg = __ldg(xpt + (size_t)(3 * Uu) * Bb);
    float c  = (t > 0) ? __ldcg(&g_c[b * Uu + u]) : 0.f;   // t=0: c0 = 0 (deterministic)

    __syncthreads();

    unsigned long long af = 0ull, ai = 0ull, ao = 0ull, ag = 0ull;
    if (t > 0) {
        const ulonglong2* hrow = (const ulonglong2*)(g_h[t & 1] + b * Uu);
        #pragma unroll 8
        for (int j = 0; j < Uu / 4; j++) {            // 4 h per iter = 2 k-pairs
            ulonglong2 h2 = __ldcg(hrow + j);         // (h0,h1),(h2,h3)
            const unsigned long long* w0 = whs + (((2 * j) << 2) + ul) * 4;
            ulonglong2 wA = *(const ulonglong2*)(w0);       // gates f,i  pair 2j
            ulonglong2 wB = *(const ulonglong2*)(w0 + 2);   // gates o,g  pair 2j
            af = ffma2(h2.x, wA.x, af);  ai = ffma2(h2.x, wA.y, ai);
            ao = ffma2(h2.x, wB.x, ao);  ag = ffma2(h2.x, wB.y, ag);
            const unsigned long long* w1 = whs + (((2 * j + 1) << 2) + ul) * 4;
            ulonglong2 wC = *(const ulonglong2*)(w1);
            ulonglong2 wD = *(const ulonglong2*)(w1 + 2);
            af = ffma2(h2.y, wC.x, af);  ai = ffma2(h2.y, wC.y, ai);
            ao = ffma2(h2.y, wD.x, ao);  ag = ffma2(h2.y, wD.y, ag);
        }
    }

    float f  = hadd2(af) + zf;
    float i_ = hadd2(ai) + zi;
    float o  = hadd2(ao) + zo;
    float g  = hadd2(ag) + zg;
    f  = 1.f / (1.f + expf(-f));
    i_ = 1.f / (1.f + expf(-i_));
    o  = 1.f / (1.f + expf(-o));
    g  = 1.f / (1.f + expf(-g));
    c = f * c + i_ * g;
    float h = tanhf(c) * o;

    g_h[(t + 1) & 1][b * Uu + u] = h;                 // read by step t+1 as g_h[(t+1)&1]
    g_c[b * Uu + u] = c;
    out[((size_t)b * Tt + t) * Uu + u] = h;
}

// =====================================================================================
extern "C" void kernel_launch(void* const* d_in, const int* in_sizes, int n_in,
                              void* d_out, int out_size)
{
    const float* inp  = (const float*)d_in[0];
    const float* Wf_x = (const float*)d_in[1];
    const float* Wf_h = (const float*)d_in[2];
    const float* bf   = (const float*)d_in[3];
    const float* Wi_x = (const float*)d_in[4];
    const float* Wi_h = (const float*)d_in[5];
    const float* bi   = (const float*)d_in[6];
    const float* Wo_x = (const float*)d_in[7];
    const float* Wo_h = (const float*)d_in[8];
    const float* bo   = (const float*)d_in[9];
    const float* Wg_x = (const float*)d_in[10];
    const float* Wg_h = (const float*)d_in[11];
    const float* bg   = (const float*)d_in[12];
    float* out = (float*)d_out;

    dim3 g1(32, Tt);
    xproj_kernel<<<g1, 256>>>(inp, Wf_x, Wi_x, Wo_x, Wg_x, bf, bi, bo, bg);
    pack_kernel<<<NBLK, 256>>>(Wf_h, Wi_h, Wo_h, Wg_h);
    for (int t = 0; t < Tt; t++)
        lstm_step_kernel<<<NBLK, 256>>>(out, t);
}

// round 5
// speedup vs baseline: 1.1175x; 1.1175x over previous
#include <cuda_runtime.h>

#define Bb 64
#define Tt 512
#define Ee 256
#define Uu 512
#define NG 2048   // 4*U
#define NBLK 128  // step-kernel grid: CTA owns 4 u-columns (all 4 gates)

// Scratch (device globals: allocation-free per harness rules)
__device__ float g_xp[(size_t)Tt * NG * Bb];          // [t][n][b], n = gate*U + u (256 MB)
__device__ float g_h[2][Bb * Uu];                     // h double buffer (L2-resident)
__device__ float g_c[Bb * Uu];                        // cell state
__device__ unsigned long long g_wpack[NBLK * 4096];   // packed Wh, per-CTA slices (4 MB)

// ---------- packed f32x2 helpers (Blackwell FFMA2; ptxas never emits these) ----------
static __device__ __forceinline__ unsigned long long pack2(float a, float b) {
    unsigned long long r;
    unsigned ai = __float_as_uint(a), bi = __float_as_uint(b);
    asm("mov.b64 %0, {%1, %2};" : "=l"(r) : "r"(ai), "r"(bi));
    return r;
}
static __device__ __forceinline__ void unpack2(unsigned long long v, float& a, float& b) {
    unsigned ai, bi;
    asm("mov.b64 {%0, %1}, %2;" : "=r"(ai), "=r"(bi) : "l"(v));
    a = __uint_as_float(ai); b = __uint_as_float(bi);
}
static __device__ __forceinline__ unsigned long long ffma2(
    unsigned long long a, unsigned long long b, unsigned long long c) {
    unsigned long long d;
    asm("fma.rn.f32x2 %0, %1, %2, %3;" : "=l"(d) : "l"(a), "l"(b), "l"(c));
    return d;
}
static __device__ __forceinline__ float hadd2(unsigned long long v) {
    float a, b; unpack2(v, a, b); return a + b;
}

// =====================================================================================
// Kernel 1: x_proj. Per block: one t, 64x64 (b x n) tile, K=256 in 4 chunks of 64.
// Output layout xp[t][n][b] (+bias) so step kernels read b-contiguous columns.
// =====================================================================================
__global__ __launch_bounds__(256) void xproj_kernel(
    const float* __restrict__ inp,
    const float* __restrict__ W0, const float* __restrict__ W1,
    const float* __restrict__ W2, const float* __restrict__ W3,
    const float* __restrict__ b0, const float* __restrict__ b1,
    const float* __restrict__ b2, const float* __restrict__ b3)
{
    __shared__ float As[64][72];   // [b][e-chunk]
    __shared__ float Ws[64][72];   // [e-chunk][n]

    const int t     = blockIdx.y;
    const int ntile = blockIdx.x;        // 0..31
    const int gate  = ntile >> 3;
    const int u0    = (ntile & 7) << 6;
    const float* W    = (gate == 0) ? W0 : (gate == 1) ? W1 : (gate == 2) ? W2 : W3;
    const float* bias = (gate == 0) ? b0 : (gate == 1) ? b1 : (gate == 2) ? b2 : b3;

    const int tid = threadIdx.x;
    const int nq  = tid & 15;            // 4 consecutive n
    const int bq  = tid >> 4;            // 4 consecutive b

    unsigned long long acc[4][2];
    #pragma unroll
    for (int i = 0; i < 4; i++) { acc[i][0] = 0ull; acc[i][1] = 0ull; }

    for (int ec = 0; ec < Ee; ec += 64) {
        {   // A tile: inputs[b][t][ec..ec+63]
            int b = tid >> 2, q = tid & 3;
            const float4* src = (const float4*)(inp + ((size_t)b * Tt + t) * Ee + ec);
            float4* dst = (float4*)&As[b][0];
            #pragma unroll
            for (int i = 0; i < 4; i++) dst[q + i * 4] = src[q + i * 4];
        }
        {   // W tile: W[ec+e][u0..u0+63]
            int er = tid >> 4, n4 = (tid & 15) << 2;
            #pragma unroll
            for (int p = 0; p < 4; p++) {
                int e = er + p * 16;
                *(float4*)&Ws[e][n4] = *(const float4*)&W[(size_t)(ec + e) * Uu + u0 + n4];
            }
        }
        __syncthreads();
        #pragma unroll 4
        for (int e = 0; e < 64; e++) {
            ulonglong2 w = *(const ulonglong2*)&Ws[e][nq << 2];
            #pragma unroll
            for (int bi = 0; bi < 4; bi++) {
                float a = As[(bq << 2) + bi][e];
                unsigned long long aa = pack2(a, a);
                acc[bi][0] = ffma2(aa, w.x, acc[bi][0]);
                acc[bi][1] = ffma2(aa, w.y, acc[bi][1]);
            }
        }
        __syncthreads();
    }

    float r[4][4];
    #pragma unroll
    for (int bi = 0; bi < 4; bi++) {
        unpack2(acc[bi][0], r[bi][0], r[bi][1]);
        unpack2(acc[bi][1], r[bi][2], r[bi][3]);
    }
    size_t base = (size_t)t * NG * Bb
                + (size_t)(gate * Uu + u0 + (nq << 2)) * Bb + (bq << 2);
    #pragma unroll
    for (int nj = 0; nj < 4; nj++) {
        float bv = bias[u0 + (nq << 2) + nj];
        float4 v = make_float4(r[0][nj] + bv, r[1][nj] + bv, r[2][nj] + bv, r[3][nj] + bv);
        *(float4*)&g_xp[base + (size_t)nj * Bb] = v;
    }
}

// =====================================================================================
// Kernel 2: pack recurrent weights once into per-CTA slices.
// g_wpack[blk*4096 + p*16 + ul*4 + g] = (W_g[2p][u], W_g[2p+1][u]), u = blk*4+ul.
// =====================================================================================
__global__ __launch_bounds__(256) void pack_kernel(
    const float* __restrict__ Wfh, const float* __restrict__ Wih,
    const float* __restrict__ Woh, const float* __restrict__ Wgh)
{
    const int blk = blockIdx.x;
    const int ubase = blk << 2;
    for (int i = threadIdx.x; i < 4096; i += 256) {
        int p = i >> 4, ul = (i >> 2) & 3, g = i & 3;
        int u = ubase + ul;
        const float* W = (g == 0) ? Wfh : (g == 1) ? Wih : (g == 2) ? Woh : Wgh;
        g_wpack[(size_t)blk * 4096 + i] =
            pack2(W[(size_t)(2 * p) * Uu + u], W[(size_t)(2 * p + 1) * Uu + u]);
    }
}

// =====================================================================================
// Kernel 3: ONE TIMESTEP, 128 CTAs x 1024 threads (32 warps/SM -> hides L2/LDS latency;
// R3 ncu showed occ 12%, issue 10% with 256 threads). Thread = (ks, b, ul): k-range
// [128*ks, 128*ks+128) of the 4 gate dots for (b, u=blk*4+ul). Partials reduced via
// smem that ALIASES the weight tile (dead after the dot loop) to stay at 32 KB static.
// Graph edge between consecutive launches is the global sync — no spin anywhere.
// =====================================================================================
__global__ __launch_bounds__(1024) void lstm_step_kernel(float* __restrict__ out, int t)
{
    __shared__ unsigned long long whs[4096];          // [p][ul][g] k-pair weights (32 KB)
    const int tid = threadIdx.x;
    const int blk = blockIdx.x;

    {   // refill weight tile: fully coalesced, hits L2
        const unsigned long long* src = g_wpack + (size_t)blk * 4096;
        #pragma unroll
        for (int j = 0; j < 4; j++)
            whs[tid + j * 1024] = __ldcg(src + tid + j * 1024);
    }

    const int ks = tid >> 8;             // k-split 0..3 (warp-uniform)
    const int r  = tid & 255;
    const int b  = r >> 2;               // 4 lanes share a b (LDG broadcast / L1 dedup)
    const int ul = r & 3;
    const int u  = (blk << 2) + ul;

    // ks==0 threads also own the pointwise tail: issue xp/c loads early
    float zf = 0.f, zi = 0.f, zo = 0.f, zg = 0.f, c = 0.f;
    if (ks == 0) {
        const float* xpt = g_xp + (size_t)t * NG * Bb + (size_t)u * Bb + b;
        zf = __ldg(xpt);
        zi = __ldg(xpt + (size_t)(1 * Uu) * Bb);
        zo = __ldg(xpt + (size_t)(2 * Uu) * Bb);
        zg = __ldg(xpt + (size_t)(3 * Uu) * Bb);
        if (t > 0) c = __ldcg(&g_c[b * Uu + u]);
    }
    __syncthreads();

    unsigned long long af = 0ull, ai = 0ull, ao = 0ull, ag = 0ull;
    if (t > 0) {
        const ulonglong2* hrow = (const ulonglong2*)(g_h[t & 1] + b * Uu) + ks * 32;
        const unsigned long long* wbase = whs + ks * 1024;   // pair index ks*64, stride 16
        #pragma unroll 8
        for (int j = 0; j < 32; j++) {                // 4 h per iter = 2 k-pairs
            ulonglong2 h2 = __ldcg(hrow + j);         // (h0,h1),(h2,h3)
            const unsigned long long* w0 = wbase + (2 * j) * 16 + ul * 4;
            ulonglong2 wA = *(const ulonglong2*)(w0);       // gates f,i
            ulonglong2 wB = *(const ulonglong2*)(w0 + 2);   // gates o,g
            af = ffma2(h2.x, wA.x, af);  ai = ffma2(h2.x, wA.y, ai);
            ao = ffma2(h2.x, wB.x, ao);  ag = ffma2(h2.x, wB.y, ag);
            const unsigned long long* w1 = w0 + 16;
            ulonglong2 wC = *(const ulonglong2*)(w1);
            ulonglong2 wD = *(const ulonglong2*)(w1 + 2);
            af = ffma2(h2.y, wC.x, af);  ai = ffma2(h2.y, wC.y, ai);
            ao = ffma2(h2.y, wD.x, ao);  ag = ffma2(h2.y, wD.y, ag);
        }
    }

    // cross-ks reduction through smem; weight tile is dead -> alias it
    __syncthreads();                                  // all reads of whs complete
    ulonglong2* red = (ulonglong2*)whs;               // [ks-1][r][2] : 3*256*2 u128
    if (ks > 0) {
        red[((ks - 1) * 256 + r) * 2 + 0] = make_ulonglong2(af, ai);
        red[((ks - 1) * 256 + r) * 2 + 1] = make_ulonglong2(ao, ag);
    }
    __syncthreads();

    if (ks == 0) {
        float f  = hadd2(af) + zf;
        float i_ = hadd2(ai) + zi;
        float o  = hadd2(ao) + zo;
        float g  = hadd2(ag) + zg;
        #pragma unroll
        for (int s = 0; s < 3; s++) {                 // scalar adds: proven-ISA only
            ulonglong2 p0 = red[(s * 256 + r) * 2 + 0];
            ulonglong2 p1 = red[(s * 256 + r) * 2 + 1];
            f  += hadd2(p0.x);  i_ += hadd2(p0.y);
            o  += hadd2(p1.x);  g  += hadd2(p1.y);
        }
        f  = 1.f / (1.f + expf(-f));
        i_ = 1.f / (1.f + expf(-i_));
        o  = 1.f / (1.f + expf(-o));
        g  = 1.f / (1.f + expf(-g));
        c = f * c + i_ * g;
        float h = tanhf(c) * o;

        g_h[(t + 1) & 1][b * Uu + u] = h;             // read by step t+1
        g_c[b * Uu + u] = c;
        out[((size_t)b * Tt + t) * Uu + u] = h;
    }
}

// =====================================================================================
extern "C" void kernel_launch(void* const* d_in, const int* in_sizes, int n_in,
                              void* d_out, int out_size)
{
    const float* inp  = (const float*)d_in[0];
    const float* Wf_x = (const float*)d_in[1];
    const float* Wf_h = (const float*)d_in[2];
    const float* bf   = (const float*)d_in[3];
    const float* Wi_x = (const float*)d_in[4];
    const float* Wi_h = (const float*)d_in[5];
    const float* bi   = (const float*)d_in[6];
    const float* Wo_x = (const float*)d_in[7];
    const float* Wo_h = (const float*)d_in[8];
    const float* bo   = (const float*)d_in[9];
    const float* Wg_x = (const float*)d_in[10];
    const float* Wg_h = (const float*)d_in[11];
    const float* bg   = (const float*)d_in[12];
    float* out = (float*)d_out;

    dim3 g1(32, Tt);
    xproj_kernel<<<g1, 256>>>(inp, Wf_x, Wi_x, Wo_x, Wg_x, bf, bi, bo, bg);
    pack_kernel<<<NBLK, 256>>>(Wf_h, Wi_h, Wo_h, Wg_h);
    for (int t = 0; t < Tt; t++)
        lstm_step_kernel<<<NBLK, 1024>>>(out, t);
}

// round 6
// speedup vs baseline: 1.1885x; 1.0635x over previous
#include <cuda_runtime.h>

#define Bb 64
#define Tt 512
#define Ee 256
#define Uu 512
#define NG 2048   // 4*U
#define NBLK 128  // step-kernel grid: CTA owns 4 u-columns (all 4 gates)

// Scratch (device globals: allocation-free per harness rules)
__device__ float g_xp[(size_t)Tt * NG * Bb];          // [t][n][b], n = gate*U + u (256 MB)
__device__ float g_h[2][Bb * Uu];                     // h double buffer (L2-resident)
__device__ float g_c[Bb * Uu];                        // cell state
__device__ unsigned long long g_wpack[NBLK * 4096];   // packed Wh, per-CTA slices (4 MB)

// ---------- packed f32x2 helpers (Blackwell FFMA2; ptxas never emits these) ----------
static __device__ __forceinline__ unsigned long long pack2(float a, float b) {
    unsigned long long r;
    unsigned ai = __float_as_uint(a), bi = __float_as_uint(b);
    asm("mov.b64 %0, {%1, %2};" : "=l"(r) : "r"(ai), "r"(bi));
    return r;
}
static __device__ __forceinline__ void unpack2(unsigned long long v, float& a, float& b) {
    unsigned ai, bi;
    asm("mov.b64 {%0, %1}, %2;" : "=r"(ai), "=r"(bi) : "l"(v));
    a = __uint_as_float(ai); b = __uint_as_float(bi);
}
static __device__ __forceinline__ unsigned long long ffma2(
    unsigned long long a, unsigned long long b, unsigned long long c) {
    unsigned long long d;
    asm("fma.rn.f32x2 %0, %1, %2, %3;" : "=l"(d) : "l"(a), "l"(b), "l"(c));
    return d;
}
static __device__ __forceinline__ float hadd2(unsigned long long v) {
    float a, b; unpack2(v, a, b); return a + b;
}

// =====================================================================================
// Kernel 1: x_proj. Per block: one t, 64x64 (b x n) tile, K=256 in 4 chunks of 64.
// Output layout xp[t][n][b] (+bias) so step kernels read b-contiguous columns.
// =====================================================================================
__global__ __launch_bounds__(256) void xproj_kernel(
    const float* __restrict__ inp,
    const float* __restrict__ W0, const float* __restrict__ W1,
    const float* __restrict__ W2, const float* __restrict__ W3,
    const float* __restrict__ b0, const float* __restrict__ b1,
    const float* __restrict__ b2, const float* __restrict__ b3)
{
    __shared__ float As[64][72];   // [b][e-chunk]
    __shared__ float Ws[64][72];   // [e-chunk][n]

    const int t     = blockIdx.y;
    const int ntile = blockIdx.x;        // 0..31
    const int gate  = ntile >> 3;
    const int u0    = (ntile & 7) << 6;
    const float* W    = (gate == 0) ? W0 : (gate == 1) ? W1 : (gate == 2) ? W2 : W3;
    const float* bias = (gate == 0) ? b0 : (gate == 1) ? b1 : (gate == 2) ? b2 : b3;

    const int tid = threadIdx.x;
    const int nq  = tid & 15;            // 4 consecutive n
    const int bq  = tid >> 4;            // 4 consecutive b

    unsigned long long acc[4][2];
    #pragma unroll
    for (int i = 0; i < 4; i++) { acc[i][0] = 0ull; acc[i][1] = 0ull; }

    for (int ec = 0; ec < Ee; ec += 64) {
        {   // A tile: inputs[b][t][ec..ec+63]
            int b = tid >> 2, q = tid & 3;
            const float4* src = (const float4*)(inp + ((size_t)b * Tt + t) * Ee + ec);
            float4* dst = (float4*)&As[b][0];
            #pragma unroll
            for (int i = 0; i < 4; i++) dst[q + i * 4] = src[q + i * 4];
        }
        {   // W tile: W[ec+e][u0..u0+63]
            int er = tid >> 4, n4 = (tid & 15) << 2;
            #pragma unroll
            for (int p = 0; p < 4; p++) {
                int e = er + p * 16;
                *(float4*)&Ws[e][n4] = *(const float4*)&W[(size_t)(ec + e) * Uu + u0 + n4];
            }
        }
        __syncthreads();
        #pragma unroll 4
        for (int e = 0; e < 64; e++) {
            ulonglong2 w = *(const ulonglong2*)&Ws[e][nq << 2];
            #pragma unroll
            for (int bi = 0; bi < 4; bi++) {
                float a = As[(bq << 2) + bi][e];
                unsigned long long aa = pack2(a, a);
                acc[bi][0] = ffma2(aa, w.x, acc[bi][0]);
                acc[bi][1] = ffma2(aa, w.y, acc[bi][1]);
            }
        }
        __syncthreads();
    }

    float r[4][4];
    #pragma unroll
    for (int bi = 0; bi < 4; bi++) {
        unpack2(acc[bi][0], r[bi][0], r[bi][1]);
        unpack2(acc[bi][1], r[bi][2], r[bi][3]);
    }
    size_t base = (size_t)t * NG * Bb
                + (size_t)(gate * Uu + u0 + (nq << 2)) * Bb + (bq << 2);
    #pragma unroll
    for (int nj = 0; nj < 4; nj++) {
        float bv = bias[u0 + (nq << 2) + nj];
        float4 v = make_float4(r[0][nj] + bv, r[1][nj] + bv, r[2][nj] + bv, r[3][nj] + bv);
        *(float4*)&g_xp[base + (size_t)nj * Bb] = v;
    }
}

// =====================================================================================
// Kernel 2: pack recurrent weights once into per-CTA slices.
// g_wpack[blk*4096 + p*16 + ul*4 + g] = (W_g[2p][u], W_g[2p+1][u]), u = blk*4+ul.
// Per warp, the 4 ul lanes' 16B reads of a given gate-pair land in ONE 128B line.
// =====================================================================================
__global__ __launch_bounds__(256) void pack_kernel(
    const float* __restrict__ Wfh, const float* __restrict__ Wih,
    const float* __restrict__ Woh, const float* __restrict__ Wgh)
{
    const int blk = blockIdx.x;
    const int ubase = blk << 2;
    for (int i = threadIdx.x; i < 4096; i += 256) {
        int p = i >> 4, ul = (i >> 2) & 3, g = i & 3;
        int u = ubase + ul;
        const float* W = (g == 0) ? Wfh : (g == 1) ? Wih : (g == 2) ? Woh : Wgh;
        g_wpack[(size_t)blk * 4096 + i] =
            pack2(W[(size_t)(2 * p) * Uu + u], W[(size_t)(2 * p + 1) * Uu + u]);
    }
}

// =====================================================================================
// Kernel 3: ONE TIMESTEP, 128 CTAs x 1024 threads. Thread = (ks, b, ul): k-range
// [128*ks, +128) of the 4 gate dots for (b, u=blk*4+ul).
// R5 fix: NO smem weight tile (prologue copy + bar was serialized latency). Weights
// read via __ldg from g_wpack -> demand-fill L1 (flushed per launch), 8x warp reuse.
// h read via __ldg with an explicit depth-4 prefetch pipeline (MLP~4) to cover L2.
// Partials reduced via a small dedicated smem buffer. Graph edge = global sync.
// =====================================================================================
__global__ __launch_bounds__(1024) void lstm_step_kernel(float* __restrict__ out, int t)
{
    __shared__ ulonglong2 red[3 * 256 * 2];           // 12 KB cross-ks partials
    const int tid = threadIdx.x;
    const int blk = blockIdx.x;

    const int ks = tid >> 8;             // k-split 0..3 (warp-uniform)
    const int r  = tid & 255;
    const int b  = r >> 2;               // 4 lanes share a b (LDG broadcast)
    const int ul = r & 3;
    const int u  = (blk << 2) + ul;

    // ks==0 threads own the pointwise tail: issue xp/c loads early
    float zf = 0.f, zi = 0.f, zo = 0.f, zg = 0.f, c = 0.f;
    if (ks == 0) {
        const float* xpt = g_xp + (size_t)t * NG * Bb + (size_t)u * Bb + b;
        zf = __ldg(xpt);
        zi = __ldg(xpt + (size_t)(1 * Uu) * Bb);
        zo = __ldg(xpt + (size_t)(2 * Uu) * Bb);
        zg = __ldg(xpt + (size_t)(3 * Uu) * Bb);
        if (t > 0) c = __ldg(&g_c[b * Uu + u]);       // L1 flushed per launch -> safe
    }

    unsigned long long af = 0ull, ai = 0ull, ao = 0ull, ag = 0ull;
    if (t > 0) {
        const ulonglong2* hrow = (const ulonglong2*)(g_h[t & 1] + b * Uu) + ks * 32;
        // weight slice for this ks: pair index ks*64 (16 u64 per pair)
        const unsigned long long* wq = g_wpack + (size_t)blk * 4096 + ks * 1024 + ul * 4;

        ulonglong2 hb0 = __ldg(hrow + 0);
        ulonglong2 hb1 = __ldg(hrow + 1);
        ulonglong2 hb2 = __ldg(hrow + 2);
        ulonglong2 hb3 = __ldg(hrow + 3);

        #pragma unroll
        for (int j4 = 0; j4 < 8; j4++) {
            ulonglong2 n0, n1, n2, n3;
            if (j4 < 7) {                             // prefetch next group first
                n0 = __ldg(hrow + 4 * j4 + 4);
                n1 = __ldg(hrow + 4 * j4 + 5);
                n2 = __ldg(hrow + 4 * j4 + 6);
                n3 = __ldg(hrow + 4 * j4 + 7);
            }
            const unsigned long long* wj = wq + (size_t)(8 * j4) * 16;
            #pragma unroll
            for (int jj = 0; jj < 4; jj++) {          // j = 4*j4+jj : 4 h = 2 k-pairs
                ulonglong2 h2 = (jj == 0) ? hb0 : (jj == 1) ? hb1 : (jj == 2) ? hb2 : hb3;
                const unsigned long long* w0 = wj + (size_t)(2 * jj) * 16;
                ulonglong2 wA = __ldg((const ulonglong2*)(w0));       // gates f,i
                ulonglong2 wB = __ldg((const ulonglong2*)(w0 + 2));   // gates o,g
                af = ffma2(h2.x, wA.x, af);  ai = ffma2(h2.x, wA.y, ai);
                ao = ffma2(h2.x, wB.x, ao);  ag = ffma2(h2.x, wB.y, ag);
                ulonglong2 wC = __ldg((const ulonglong2*)(w0 + 16));
                ulonglong2 wD = __ldg((const ulonglong2*)(w0 + 18));
                af = ffma2(h2.y, wC.x, af);  ai = ffma2(h2.y, wC.y, ai);
                ao = ffma2(h2.y, wD.x, ao);  ag = ffma2(h2.y, wD.y, ag);
            }
            hb0 = n0; hb1 = n1; hb2 = n2; hb3 = n3;
        }
    }

    // cross-ks reduction through smem
    if (ks > 0) {
        red[((ks - 1) * 256 + r) * 2 + 0] = make_ulonglong2(af, ai);
        red[((ks - 1) * 256 + r) * 2 + 1] = make_ulonglong2(ao, ag);
    }
    __syncthreads();

    if (ks == 0) {
        float f  = hadd2(af) + zf;
        float i_ = hadd2(ai) + zi;
        float o  = hadd2(ao) + zo;
        float g  = hadd2(ag) + zg;
        #pragma unroll
        for (int s = 0; s < 3; s++) {
            ulonglong2 p0 = red[(s * 256 + r) * 2 + 0];
            ulonglong2 p1 = red[(s * 256 + r) * 2 + 1];
            f  += hadd2(p0.x);  i_ += hadd2(p0.y);
            o  += hadd2(p1.x);  g  += hadd2(p1.y);
        }
        f  = 1.f / (1.f + expf(-f));
        i_ = 1.f / (1.f + expf(-i_));
        o  = 1.f / (1.f + expf(-o));
        g  = 1.f / (1.f + expf(-g));
        c = f * c + i_ * g;
        float h = tanhf(c) * o;

        g_h[(t + 1) & 1][b * Uu + u] = h;             // read by step t+1
        g_c[b * Uu + u] = c;
        out[((size_t)b * Tt + t) * Uu + u] = h;
    }
}

// =====================================================================================
extern "C" void kernel_launch(void* const* d_in, const int* in_sizes, int n_in,
                              void* d_out, int out_size)
{
    const float* inp  = (const float*)d_in[0];
    const float* Wf_x = (const float*)d_in[1];
    const float* Wf_h = (const float*)d_in[2];
    const float* bf   = (const float*)d_in[3];
    const float* Wi_x = (const float*)d_in[4];
    const float* Wi_h = (const float*)d_in[5];
    const float* bi   = (const float*)d_in[6];
    const float* Wo_x = (const float*)d_in[7];
    const float* Wo_h = (const float*)d_in[8];
    const float* bo   = (const float*)d_in[9];
    const float* Wg_x = (const float*)d_in[10];
    const float* Wg_h = (const float*)d_in[11];
    const float* bg   = (const float*)d_in[12];
    float* out = (float*)d_out;

    dim3 g1(32, Tt);
    xproj_kernel<<<g1, 256>>>(inp, Wf_x, Wi_x, Wo_x, Wg_x, bf, bi, bo, bg);
    pack_kernel<<<NBLK, 256>>>(Wf_h, Wi_h, Wo_h, Wg_h);
    for (int t = 0; t < Tt; t++)
        lstm_step_kernel<<<NBLK, 1024>>>(out, t);
}

// round 7
// speedup vs baseline: 1.2883x; 1.0840x over previous
#include <cuda_runtime.h>

#define Bb 64
#define Tt 512
#define Ee 256
#define Uu 512
#define NG 2048   // 4*U
#define NBLK 128  // step-kernel grid: CTA owns 4 u-columns (all 4 gates)

// Scratch (device globals: allocation-free per harness rules)
__device__ float g_xp[(size_t)Tt * NG * Bb];          // [t][n][b], n = gate*U + u (256 MB)
__device__ unsigned long long g_hX[2][256 * Bb];      // h, k-pair transposed: [p][b] =
                                                      //   (h[b][2p], h[b][2p+1])  (2x128KB)
__device__ float g_c[Bb * Uu];                        // cell state
__device__ unsigned long long g_wpack[NBLK * 4096];   // packed Wh, per-CTA slices (4 MB)

// ---------- packed f32x2 helpers (Blackwell FFMA2; ptxas never emits these) ----------
static __device__ __forceinline__ unsigned long long pack2(float a, float b) {
    unsigned long long r;
    unsigned ai = __float_as_uint(a), bi = __float_as_uint(b);
    asm("mov.b64 %0, {%1, %2};" : "=l"(r) : "r"(ai), "r"(bi));
    return r;
}
static __device__ __forceinline__ void unpack2(unsigned long long v, float& a, float& b) {
    unsigned ai, bi;
    asm("mov.b64 {%0, %1}, %2;" : "=r"(ai), "=r"(bi) : "l"(v));
    a = __uint_as_float(ai); b = __uint_as_float(bi);
}
static __device__ __forceinline__ unsigned long long ffma2(
    unsigned long long a, unsigned long long b, unsigned long long c) {
    unsigned long long d;
    asm("fma.rn.f32x2 %0, %1, %2, %3;" : "=l"(d) : "l"(a), "l"(b), "l"(c));
    return d;
}
static __device__ __forceinline__ float hadd2(unsigned long long v) {
    float a, b; unpack2(v, a, b); return a + b;
}

// =====================================================================================
// Kernel 1: x_proj. Per block: one t, 64x64 (b x n) tile, K=256 in 4 chunks of 64.
// Output layout xp[t][n][b] (+bias) so step kernels read b-contiguous columns.
// =====================================================================================
__global__ __launch_bounds__(256) void xproj_kernel(
    const float* __restrict__ inp,
    const float* __restrict__ W0, const float* __restrict__ W1,
    const float* __restrict__ W2, const float* __restrict__ W3,
    const float* __restrict__ b0, const float* __restrict__ b1,
    const float* __restrict__ b2, const float* __restrict__ b3)
{
    __shared__ float As[64][72];   // [b][e-chunk]
    __shared__ float Ws[64][72];   // [e-chunk][n]

    const int t     = blockIdx.y;
    const int ntile = blockIdx.x;        // 0..31
    const int gate  = ntile >> 3;
    const int u0    = (ntile & 7) << 6;
    const float* W    = (gate == 0) ? W0 : (gate == 1) ? W1 : (gate == 2) ? W2 : W3;
    const float* bias = (gate == 0) ? b0 : (gate == 1) ? b1 : (gate == 2) ? b2 : b3;

    const int tid = threadIdx.x;
    const int nq  = tid & 15;            // 4 consecutive n
    const int bq  = tid >> 4;            // 4 consecutive b

    unsigned long long acc[4][2];
    #pragma unroll
    for (int i = 0; i < 4; i++) { acc[i][0] = 0ull; acc[i][1] = 0ull; }

    for (int ec = 0; ec < Ee; ec += 64) {
        {   // A tile: inputs[b][t][ec..ec+63]
            int b = tid >> 2, q = tid & 3;
            const float4* src = (const float4*)(inp + ((size_t)b * Tt + t) * Ee + ec);
            float4* dst = (float4*)&As[b][0];
            #pragma unroll
            for (int i = 0; i < 4; i++) dst[q + i * 4] = src[q + i * 4];
        }
        {   // W tile: W[ec+e][u0..u0+63]
            int er = tid >> 4, n4 = (tid & 15) << 2;
            #pragma unroll
            for (int p = 0; p < 4; p++) {
                int e = er + p * 16;
                *(float4*)&Ws[e][n4] = *(const float4*)&W[(size_t)(ec + e) * Uu + u0 + n4];
            }
        }
        __syncthreads();
        #pragma unroll 4
        for (int e = 0; e < 64; e++) {
            ulonglong2 w = *(const ulonglong2*)&Ws[e][nq << 2];
            #pragma unroll
            for (int bi = 0; bi < 4; bi++) {
                float a = As[(bq << 2) + bi][e];
                unsigned long long aa = pack2(a, a);
                acc[bi][0] = ffma2(aa, w.x, acc[bi][0]);
                acc[bi][1] = ffma2(aa, w.y, acc[bi][1]);
            }
        }
        __syncthreads();
    }

    float r[4][4];
    #pragma unroll
    for (int bi = 0; bi < 4; bi++) {
        unpack2(acc[bi][0], r[bi][0], r[bi][1]);
        unpack2(acc[bi][1], r[bi][2], r[bi][3]);
    }
    size_t base = (size_t)t * NG * Bb
                + (size_t)(gate * Uu + u0 + (nq << 2)) * Bb + (bq << 2);
    #pragma unroll
    for (int nj = 0; nj < 4; nj++) {
        float bv = bias[u0 + (nq << 2) + nj];
        float4 v = make_float4(r[0][nj] + bv, r[1][nj] + bv, r[2][nj] + bv, r[3][nj] + bv);
        *(float4*)&g_xp[base + (size_t)nj * Bb] = v;
    }
}

// =====================================================================================
// Kernel 2: pack recurrent weights once into per-CTA slices.
// g_wpack[blk*4096 + p*16 + ul*4 + g] = (W_g[2p][u], W_g[2p+1][u]), u = blk*4+ul.
// Per warp, the 4 ul lanes' 16B reads of a given gate-pair land in ONE 128B line.
// =====================================================================================
__global__ __launch_bounds__(256) void pack_kernel(
    const float* __restrict__ Wfh, const float* __restrict__ Wih,
    const float* __restrict__ Woh, const float* __restrict__ Wgh)
{
    const int blk = blockIdx.x;
    const int ubase = blk << 2;
    for (int i = threadIdx.x; i < 4096; i += 256) {
        int p = i >> 4, ul = (i >> 2) & 3, g = i & 3;
        int u = ubase + ul;
        const float* W = (g == 0) ? Wfh : (g == 1) ? Wih : (g == 2) ? Woh : Wgh;
        g_wpack[(size_t)blk * 4096 + i] =
            pack2(W[(size_t)(2 * p) * Uu + u], W[(size_t)(2 * p + 1) * Uu + u]);
    }
}

// =====================================================================================
// Kernel 3: ONE TIMESTEP, 128 CTAs x 1024 threads. Thread = (ks, b, ul): k-range
// [128*ks, +128) of the 4 gate dots for (b, u=blk*4+ul).
// R6 fix: h stored k-pair-TRANSPOSED (g_hX[p][b] = u64 pair). A warp's h read at
// fixed p spans 8 adjacent b = 64B contiguous = 1 L1 wavefront (was 8 per LDG.128;
// h wavefronts/CTA drop 8192 -> 2048; kernel was L1-wavefront-bound at L1=61%).
// Weights via __ldg from g_wpack (demand-fill L1, 8-warp reuse, 1 wf per LDG.128).
// Partials reduced via a small smem buffer. Graph edge = global sync, no spin.
// =====================================================================================
__global__ __launch_bounds__(1024) void lstm_step_kernel(float* __restrict__ out, int t)
{
    __shared__ ulonglong2 red[3 * 256 * 2];           // 12 KB cross-ks partials
    const int tid = threadIdx.x;
    const int blk = blockIdx.x;

    const int ks = tid >> 8;             // k-split 0..3 (warp-uniform)
    const int r  = tid & 255;
    const int b  = r >> 2;               // 4 lanes share a b
    const int ul = r & 3;
    const int u  = (blk << 2) + ul;

    // ks==0 threads own the pointwise tail: issue xp/c loads early
    float zf = 0.f, zi = 0.f, zo = 0.f, zg = 0.f, c = 0.f;
    if (ks == 0) {
        const float* xpt = g_xp + (size_t)t * NG * Bb + (size_t)u * Bb + b;
        zf = __ldg(xpt);
        zi = __ldg(xpt + (size_t)(1 * Uu) * Bb);
        zo = __ldg(xpt + (size_t)(2 * Uu) * Bb);
        zg = __ldg(xpt + (size_t)(3 * Uu) * Bb);
        if (t > 0) c = __ldg(&g_c[b * Uu + u]);       // L1 flushed per launch -> safe
    }

    unsigned long long af = 0ull, ai = 0ull, ao = 0ull, ag = 0ull;
    if (t > 0) {
        // h pairs for this thread: g_hX[t&1][p][b], p = ks*64 + j   (stride 64 u64)
        const unsigned long long* hp = g_hX[t & 1] + (size_t)(ks * 64) * Bb + b;
        // weight slice: pair index ks*64, 16 u64 per pair, gate-pair at ul*4
        const unsigned long long* wq = g_wpack + (size_t)blk * 4096 + ks * 1024 + ul * 4;

        #pragma unroll 8
        for (int j = 0; j < 64; j++) {                // one k-pair per iter
            unsigned long long h2 = __ldg(hp + (size_t)j * Bb);
            ulonglong2 wA = __ldg((const ulonglong2*)(wq + (size_t)j * 16));      // f,i
            ulonglong2 wB = __ldg((const ulonglong2*)(wq + (size_t)j * 16 + 2));  // o,g
            af = ffma2(h2, wA.x, af);  ai = ffma2(h2, wA.y, ai);
            ao = ffma2(h2, wB.x, ao);  ag = ffma2(h2, wB.y, ag);
        }
    }

    // cross-ks reduction through smem
    if (ks > 0) {
        red[((ks - 1) * 256 + r) * 2 + 0] = make_ulonglong2(af, ai);
        red[((ks - 1) * 256 + r) * 2 + 1] = make_ulonglong2(ao, ag);
    }
    __syncthreads();

    if (ks == 0) {
        float f  = hadd2(af) + zf;
        float i_ = hadd2(ai) + zi;
        float o  = hadd2(ao) + zo;
        float g  = hadd2(ag) + zg;
        #pragma unroll
        for (int s = 0; s < 3; s++) {
            ulonglong2 p0 = red[(s * 256 + r) * 2 + 0];
            ulonglong2 p1 = red[(s * 256 + r) * 2 + 1];
            f  += hadd2(p0.x);  i_ += hadd2(p0.y);
            o  += hadd2(p1.x);  g  += hadd2(p1.y);
        }
        f  = 1.f / (1.f + expf(-f));
        i_ = 1.f / (1.f + expf(-i_));
        o  = 1.f / (1.f + expf(-o));
        g  = 1.f / (1.f + expf(-g));
        c = f * c + i_ * g;
        float h = tanhf(c) * o;

        // store h into the k-pair-transposed layout for step t+1:
        // float element (p=u>>1, b, half=u&1) at index ((u>>1)*Bb + b)*2 + (u&1)
        float* hXf = (float*)g_hX[(t + 1) & 1];
        hXf[(size_t)((u >> 1) * Bb + b) * 2 + (u & 1)] = h;
        g_c[b * Uu + u] = c;
        out[((size_t)b * Tt + t) * Uu + u] = h;
    }
}

// =====================================================================================
extern "C" void kernel_launch(void* const* d_in, const int* in_sizes, int n_in,
                              void* d_out, int out_size)
{
    const float* inp  = (const float*)d_in[0];
    const float* Wf_x = (const float*)d_in[1];
    const float* Wf_h = (const float*)d_in[2];
    const float* bf   = (const float*)d_in[3];
    const float* Wi_x = (const float*)d_in[4];
    const float* Wi_h = (const float*)d_in[5];
    const float* bi   = (const float*)d_in[6];
    const float* Wo_x = (const float*)d_in[7];
    const float* Wo_h = (const float*)d_in[8];
    const float* bo   = (const float*)d_in[9];
    const float* Wg_x = (const float*)d_in[10];
    const float* Wg_h = (const float*)d_in[11];
    const float* bg   = (const float*)d_in[12];
    float* out = (float*)d_out;

    dim3 g1(32, Tt);
    xproj_kernel<<<g1, 256>>>(inp, Wf_x, Wi_x, Wo_x, Wg_x, bf, bi, bo, bg);
    pack_kernel<<<NBLK, 256>>>(Wf_h, Wi_h, Wo_h, Wg_h);
    for (int t = 0; t < Tt; t++)
        lstm_step_kernel<<<NBLK, 1024>>>(out, t);
}